// round 1
// baseline (speedup 1.0000x reference)
#include <cuda_runtime.h>
#include <cuda_bf16.h>
#include <cstdint>

// Sinkhorn, linear domain:
//   K = valid ? exp(m/tau) : 0      (stored in d_out as scratch)
//   repeat 10x: u_i = 1/sum_j K_ij v_j ;  v_j = 1/sum_i K_ij u_i
//   out = valid ? u_i * K_ij * v_j : 0   (in place; invalid already 0)
//
// B=64, N=1024, M=1024, tau=1, 10 scan steps (20 half-iterations).

#define BB 64
#define NN 1024
#define MM 1024
#define NCHUNK 4   // row chunks for col-pass partial sums

__device__ float g_u[BB * NN];
__device__ float g_v[BB * MM];
__device__ float g_vp[NCHUNK][BB * MM];

// ---------------------------------------------------------------------------
// Build K = valid ? exp(m) : 0. One block = 16 rows of one batch.
// grid = 64 batches * 64 blocks = 4096, block = 256 threads, 16 float4/thread.
// ---------------------------------------------------------------------------
__global__ void build_k_kernel(const float* __restrict__ m,
                               const int* __restrict__ nrows,
                               const int* __restrict__ ncols,
                               float* __restrict__ K) {
    int b   = blockIdx.x >> 6;
    int sub = blockIdx.x & 63;           // 16-row slab within the batch
    int nr = nrows[b];
    int nc = ncols[b];
    const float* mb = m + ((size_t)b << 20);
    float*       Kb = K + ((size_t)b << 20);

    #pragma unroll
    for (int k = 0; k < 16; k++) {
        int q = sub * 4096 + k * 256 + threadIdx.x;  // float4 index in batch
        int i = q >> 8;          // row
        int j = (q & 255) << 2;  // first column of the float4
        float4 out;
        if (i >= nr || j >= nc) {
            out = make_float4(0.f, 0.f, 0.f, 0.f);
        } else {
            float4 v = *reinterpret_cast<const float4*>(mb + ((size_t)q << 2));
            out.x = __expf(v.x);
            out.y = (j + 1 < nc) ? __expf(v.y) : 0.f;
            out.z = (j + 2 < nc) ? __expf(v.z) : 0.f;
            out.w = (j + 3 < nc) ? __expf(v.w) : 0.f;
        }
        *reinterpret_cast<float4*>(Kb + ((size_t)q << 2)) = out;
    }
}

// v := 1 everywhere (initial column potential exp(-0))
__global__ void init_v_kernel() {
    int idx = blockIdx.x * blockDim.x + threadIdx.x;
    if (idx < BB * MM) g_v[idx] = 1.0f;
}

// ---------------------------------------------------------------------------
// Row pass: u_i = 1 / sum_{j<nc} K_ij * v_j.  One warp per row.
// grid = 64*1024/8 = 8192 blocks of 256 threads (8 warps).
// ---------------------------------------------------------------------------
__global__ void row_pass_kernel(const float* __restrict__ K,
                                const int* __restrict__ nrows,
                                const int* __restrict__ ncols) {
    int gw   = (blockIdx.x * blockDim.x + threadIdx.x) >> 5;
    int lane = threadIdx.x & 31;
    int b = gw >> 10;
    int i = gw & 1023;
    int nr = nrows[b];
    if (i >= nr) {
        if (lane == 0) g_u[b * NN + i] = 0.f;
        return;
    }
    int nc = ncols[b];
    const float4* Krow = reinterpret_cast<const float4*>(K + ((size_t)b << 20) + ((size_t)i << 10));
    const float4* Vrow = reinterpret_cast<const float4*>(g_v + b * MM);

    float sum = 0.f;
    int nc4 = nc >> 2;   // fully-valid float4 count
    #pragma unroll 4
    for (int q = lane; q < nc4; q += 32) {
        float4 k4 = Krow[q];
        float4 v4 = Vrow[q];
        sum += k4.x * v4.x + k4.y * v4.y + k4.z * v4.z + k4.w * v4.w;
    }
    int rem = nc - (nc4 << 2);
    if (lane < rem) {
        int j = (nc4 << 2) + lane;
        sum += K[((size_t)b << 20) + ((size_t)i << 10) + j] * g_v[b * MM + j];
    }
    #pragma unroll
    for (int o = 16; o; o >>= 1) sum += __shfl_xor_sync(0xffffffffu, sum, o);
    if (lane == 0) g_u[b * NN + i] = (sum > 0.f) ? (1.0f / sum) : 0.f;
}

// ---------------------------------------------------------------------------
// Col pass (partials): for row chunk ch, g_vp[ch][b,j] = sum over rows in
// chunk of K_ij * u_i.  One thread per column, 256 cols per block.
// grid = 64 batches * 4 jtiles * 4 chunks = 1024 blocks.
// ---------------------------------------------------------------------------
__global__ void col_pass_kernel(const float* __restrict__ K,
                                const int* __restrict__ nrows,
                                const int* __restrict__ ncols) {
    int b  = blockIdx.x >> 4;
    int jt = (blockIdx.x >> 2) & 3;
    int ch = blockIdx.x & 3;
    int j = (jt << 8) + threadIdx.x;
    int nc = ncols[b];
    int nr = nrows[b];

    int i0 = ch << 8;
    int i1 = min(i0 + 256, nr);

    float sum = 0.f;
    if (j < nc) {
        const float* Kcol = K + ((size_t)b << 20) + j;
        const float* up   = g_u + b * NN;
        int i = i0;
        for (; i + 8 <= i1; i += 8) {
            float4 ua = *reinterpret_cast<const float4*>(up + i);
            float4 ub = *reinterpret_cast<const float4*>(up + i + 4);
            sum += Kcol[(size_t)(i + 0) << 10] * ua.x;
            sum += Kcol[(size_t)(i + 1) << 10] * ua.y;
            sum += Kcol[(size_t)(i + 2) << 10] * ua.z;
            sum += Kcol[(size_t)(i + 3) << 10] * ua.w;
            sum += Kcol[(size_t)(i + 4) << 10] * ub.x;
            sum += Kcol[(size_t)(i + 5) << 10] * ub.y;
            sum += Kcol[(size_t)(i + 6) << 10] * ub.z;
            sum += Kcol[(size_t)(i + 7) << 10] * ub.w;
        }
        for (; i < i1; ++i)
            sum += Kcol[(size_t)i << 10] * up[i];
        g_vp[ch][b * MM + j] = sum;
    }
}

// Combine partials -> v_j = 1/sum (0 outside valid cols)
__global__ void combine_v_kernel(const int* __restrict__ ncols) {
    int idx = blockIdx.x * blockDim.x + threadIdx.x;  // 0..65535
    int b = idx >> 10;
    int j = idx & 1023;
    if (j >= ncols[b]) { g_v[idx] = 0.f; return; }
    float s = g_vp[0][idx] + g_vp[1][idx] + g_vp[2][idx] + g_vp[3][idx];
    g_v[idx] = (s > 0.f) ? (1.0f / s) : 0.f;
}

// ---------------------------------------------------------------------------
// Final: out_ij = u_i * K_ij * v_j in place for valid region.
// Invalid region is already 0 from build_k. One warp per row.
// ---------------------------------------------------------------------------
__global__ void final_kernel(float* __restrict__ K,
                             const int* __restrict__ nrows,
                             const int* __restrict__ ncols) {
    int gw   = (blockIdx.x * blockDim.x + threadIdx.x) >> 5;
    int lane = threadIdx.x & 31;
    int b = gw >> 10;
    int i = gw & 1023;
    int nr = nrows[b];
    if (i >= nr) return;
    int nc = ncols[b];
    float u = g_u[b * NN + i];

    float4* Krow = reinterpret_cast<float4*>(K + ((size_t)b << 20) + ((size_t)i << 10));
    const float4* Vrow = reinterpret_cast<const float4*>(g_v + b * MM);

    int nc4 = nc >> 2;
    #pragma unroll 4
    for (int q = lane; q < nc4; q += 32) {
        float4 k4 = Krow[q];
        float4 v4 = Vrow[q];
        k4.x = k4.x * u * v4.x;
        k4.y = k4.y * u * v4.y;
        k4.z = k4.z * u * v4.z;
        k4.w = k4.w * u * v4.w;
        Krow[q] = k4;
    }
    int rem = nc - (nc4 << 2);
    if (lane < rem) {
        int j = (nc4 << 2) + lane;
        size_t off = ((size_t)b << 20) + ((size_t)i << 10) + j;
        K[off] = K[off] * u * g_v[b * MM + j];
    }
}

extern "C" void kernel_launch(void* const* d_in, const int* in_sizes, int n_in,
                              void* d_out, int out_size) {
    const float* m     = (const float*)d_in[0];
    const int*   nrows = (const int*)d_in[1];
    const int*   ncols = (const int*)d_in[2];
    float* K = (float*)d_out;   // d_out doubles as K scratch

    build_k_kernel<<<4096, 256>>>(m, nrows, ncols, K);
    init_v_kernel<<<256, 256>>>();

    for (int t = 0; t < 10; t++) {
        row_pass_kernel<<<8192, 256>>>(K, nrows, ncols);
        col_pass_kernel<<<1024, 256>>>(K, nrows, ncols);
        combine_v_kernel<<<256, 256>>>(ncols);
    }

    final_kernel<<<8192, 256>>>(K, nrows, ncols);
}

// round 2
// speedup vs baseline: 1.1521x; 1.1521x over previous
#include <cuda_runtime.h>
#include <cuda_bf16.h>
#include <cstdint>

// Sinkhorn, linear domain:
//   K = valid ? exp(m/tau) : 0      (stored in d_out as scratch)
//   repeat 10x: u_i = 1/sum_j K_ij v_j ;  v_j = 1/sum_i K_ij u_i
//   out = valid ? u_i * K_ij * v_j : 0   (in place; invalid already 0)
//
// B=64, N=1024, M=1024, tau=1, 10 scan steps (20 half-iterations).

#define BB 64
#define NN 1024
#define MM 1024
#define NCHUNK 16        // row chunks for col-pass partial sums (64 rows each)
#define CHROWS 64

__device__ float g_u[BB * NN];
__device__ float g_v[BB * MM];
__device__ float g_vp[NCHUNK][BB * MM];

// ---------------------------------------------------------------------------
// Build K = valid ? exp(m) : 0. One block = 16 rows of one batch.
// grid = 64 batches * 64 blocks = 4096, block = 256 threads, 16 float4/thread.
// ---------------------------------------------------------------------------
__global__ void build_k_kernel(const float* __restrict__ m,
                               const int* __restrict__ nrows,
                               const int* __restrict__ ncols,
                               float* __restrict__ K) {
    int b   = blockIdx.x >> 6;
    int sub = blockIdx.x & 63;           // 16-row slab within the batch
    int nr = nrows[b];
    int nc = ncols[b];
    const float* mb = m + ((size_t)b << 20);
    float*       Kb = K + ((size_t)b << 20);

    #pragma unroll
    for (int k = 0; k < 16; k++) {
        int q = sub * 4096 + k * 256 + threadIdx.x;  // float4 index in batch
        int i = q >> 8;          // row
        int j = (q & 255) << 2;  // first column of the float4
        float4 out;
        if (i >= nr || j >= nc) {
            out = make_float4(0.f, 0.f, 0.f, 0.f);
        } else {
            float4 v = *reinterpret_cast<const float4*>(mb + ((size_t)q << 2));
            out.x = __expf(v.x);
            out.y = (j + 1 < nc) ? __expf(v.y) : 0.f;
            out.z = (j + 2 < nc) ? __expf(v.z) : 0.f;
            out.w = (j + 3 < nc) ? __expf(v.w) : 0.f;
        }
        *reinterpret_cast<float4*>(Kb + ((size_t)q << 2)) = out;
    }
}

// v := 1 everywhere (initial column potential exp(-0))
__global__ void init_v_kernel() {
    int idx = blockIdx.x * blockDim.x + threadIdx.x;
    if (idx < BB * MM) g_v[idx] = 1.0f;
}

// ---------------------------------------------------------------------------
// Row pass: u_i = 1 / sum_{j<nc} K_ij * v_j.  One warp per row.
// grid = 64*1024/8 = 8192 blocks of 256 threads (8 warps).
// ---------------------------------------------------------------------------
__global__ void row_pass_kernel(const float* __restrict__ K,
                                const int* __restrict__ nrows,
                                const int* __restrict__ ncols) {
    int gw   = (blockIdx.x * blockDim.x + threadIdx.x) >> 5;
    int lane = threadIdx.x & 31;
    int b = gw >> 10;
    int i = gw & 1023;
    int nr = nrows[b];
    if (i >= nr) {
        if (lane == 0) g_u[b * NN + i] = 0.f;
        return;
    }
    int nc = ncols[b];
    const float4* Krow = reinterpret_cast<const float4*>(K + ((size_t)b << 20) + ((size_t)i << 10));
    const float4* Vrow = reinterpret_cast<const float4*>(g_v + b * MM);

    float sum = 0.f;
    int nc4 = nc >> 2;   // fully-valid float4 count
    #pragma unroll 4
    for (int q = lane; q < nc4; q += 32) {
        float4 k4 = Krow[q];
        float4 v4 = Vrow[q];
        sum += k4.x * v4.x + k4.y * v4.y + k4.z * v4.z + k4.w * v4.w;
    }
    int rem = nc - (nc4 << 2);
    if (lane < rem) {
        int j = (nc4 << 2) + lane;
        sum += K[((size_t)b << 20) + ((size_t)i << 10) + j] * g_v[b * MM + j];
    }
    #pragma unroll
    for (int o = 16; o; o >>= 1) sum += __shfl_xor_sync(0xffffffffu, sum, o);
    if (lane == 0) g_u[b * NN + i] = (sum > 0.f) ? (1.0f / sum) : 0.f;
}

// ---------------------------------------------------------------------------
// Col pass (partials): for 64-row chunk ch, g_vp[ch][b,j] = sum over rows in
// chunk of K_ij * u_i.  One thread per column, 256 cols per block.
// grid = 64 batches * 4 jtiles * 16 chunks = 4096 blocks.
// ---------------------------------------------------------------------------
__global__ void col_pass_kernel(const float* __restrict__ K,
                                const int* __restrict__ nrows,
                                const int* __restrict__ ncols) {
    int b  = blockIdx.x >> 6;
    int jt = (blockIdx.x >> 4) & 3;
    int ch = blockIdx.x & 15;
    int j = (jt << 8) + threadIdx.x;
    int nc = ncols[b];
    if (j >= nc) return;     // combine_v never reads these slots

    int nr = nrows[b];
    int i0 = ch * CHROWS;
    int i1 = min(i0 + CHROWS, nr);

    float sum = 0.f;
    const float* Kb = K + ((size_t)b << 20);
    const float* up = g_u + b * NN;
    int i = i0;
    for (; i + 8 <= i1; i += 8) {
        float4 ua = *reinterpret_cast<const float4*>(up + i);
        float4 ub = *reinterpret_cast<const float4*>(up + i + 4);
        sum = fmaf(Kb[((i + 0) << 10) + j], ua.x, sum);
        sum = fmaf(Kb[((i + 1) << 10) + j], ua.y, sum);
        sum = fmaf(Kb[((i + 2) << 10) + j], ua.z, sum);
        sum = fmaf(Kb[((i + 3) << 10) + j], ua.w, sum);
        sum = fmaf(Kb[((i + 4) << 10) + j], ub.x, sum);
        sum = fmaf(Kb[((i + 5) << 10) + j], ub.y, sum);
        sum = fmaf(Kb[((i + 6) << 10) + j], ub.z, sum);
        sum = fmaf(Kb[((i + 7) << 10) + j], ub.w, sum);
    }
    for (; i < i1; ++i)
        sum = fmaf(Kb[(i << 10) + j], up[i], sum);
    g_vp[ch][b * MM + j] = sum;
}

// Combine partials -> v_j = 1/sum (0 outside valid cols)
__global__ void combine_v_kernel(const int* __restrict__ ncols) {
    int idx = blockIdx.x * blockDim.x + threadIdx.x;  // 0..65535
    int b = idx >> 10;
    int j = idx & 1023;
    if (j >= ncols[b]) { g_v[idx] = 0.f; return; }
    float s = 0.f;
    #pragma unroll
    for (int c = 0; c < NCHUNK; c++) s += g_vp[c][idx];
    g_v[idx] = (s > 0.f) ? (1.0f / s) : 0.f;
}

// ---------------------------------------------------------------------------
// Final: out_ij = u_i * K_ij * v_j in place for valid region.
// Invalid region is already 0 from build_k. One warp per row.
// ---------------------------------------------------------------------------
__global__ void final_kernel(float* __restrict__ K,
                             const int* __restrict__ nrows,
                             const int* __restrict__ ncols) {
    int gw   = (blockIdx.x * blockDim.x + threadIdx.x) >> 5;
    int lane = threadIdx.x & 31;
    int b = gw >> 10;
    int i = gw & 1023;
    int nr = nrows[b];
    if (i >= nr) return;
    int nc = ncols[b];
    float u = g_u[b * NN + i];

    float4* Krow = reinterpret_cast<float4*>(K + ((size_t)b << 20) + ((size_t)i << 10));
    const float4* Vrow = reinterpret_cast<const float4*>(g_v + b * MM);

    int nc4 = nc >> 2;
    #pragma unroll 4
    for (int q = lane; q < nc4; q += 32) {
        float4 k4 = Krow[q];
        float4 v4 = Vrow[q];
        k4.x = k4.x * u * v4.x;
        k4.y = k4.y * u * v4.y;
        k4.z = k4.z * u * v4.z;
        k4.w = k4.w * u * v4.w;
        Krow[q] = k4;
    }
    int rem = nc - (nc4 << 2);
    if (lane < rem) {
        int j = (nc4 << 2) + lane;
        size_t off = ((size_t)b << 20) + ((size_t)i << 10) + j;
        K[off] = K[off] * u * g_v[b * MM + j];
    }
}

extern "C" void kernel_launch(void* const* d_in, const int* in_sizes, int n_in,
                              void* d_out, int out_size) {
    const float* m     = (const float*)d_in[0];
    const int*   nrows = (const int*)d_in[1];
    const int*   ncols = (const int*)d_in[2];
    float* K = (float*)d_out;   // d_out doubles as K scratch

    build_k_kernel<<<4096, 256>>>(m, nrows, ncols, K);
    init_v_kernel<<<256, 256>>>();

    for (int t = 0; t < 10; t++) {
        row_pass_kernel<<<8192, 256>>>(K, nrows, ncols);
        col_pass_kernel<<<4096, 256>>>(K, nrows, ncols);
        combine_v_kernel<<<256, 256>>>(ncols);
    }

    final_kernel<<<8192, 256>>>(K, nrows, ncols);
}

// round 3
// speedup vs baseline: 1.5163x; 1.3161x over previous
#include <cuda_runtime.h>
#include <cuda_fp16.h>
#include <cstdint>

// Sinkhorn, linear domain, fp16-compressed kernel matrix:
//   K = valid ? fp16(exp(m)) : 0            (device-global scratch)
//   10x: { u_i = 1/sum_j K_ij v_j ; v_j = 1/sum_i K_ij u_i }   (fused, K read once)
//   out = valid ? u_i * exp(m_ij) * v_j : 0  (fp32 recompute of exp — fp16 never
//                                             touches the output directly)
// B=64, N=1024, M=1024, tau=1.

#define BB 64
#define NN 1024
#define MM 1024

__device__ __half g_K[(size_t)BB * NN * MM];   // 128 MB scratch
__device__ float  g_u[BB * NN];
__device__ float  g_v[BB * MM];
__device__ float  g_s[BB * MM];                // col-sum accumulator (zeroed by combine)

// ---------------------------------------------------------------------------
// Build K fp16 = valid ? exp(m) : 0. Writes only rows < nr and col tiles
// < ceil(nc/128)*128 (the exact region the fused pass reads), zero-padding
// the tail of the last tile. grid = (512, 64), block = 256 (2 rows/block).
// ---------------------------------------------------------------------------
__global__ void build_k_kernel(const float* __restrict__ m,
                               const int* __restrict__ nrows,
                               const int* __restrict__ ncols) {
    int b  = blockIdx.y;
    int nr = nrows[b];
    int nc = ncols[b];
    int row = blockIdx.x * 2 + (threadIdx.x >> 7);
    if (row >= nr) return;
    int ncpad = (nc + 127) & ~127;
    int j = (threadIdx.x & 127) * 8;
    if (j >= ncpad) return;

    const float* mrow = m + ((size_t)b << 20) + ((size_t)row << 10);
    __half hk[8];
    if (j + 8 <= nc) {
        float4 a = *reinterpret_cast<const float4*>(mrow + j);
        float4 c = *reinterpret_cast<const float4*>(mrow + j + 4);
        hk[0] = __float2half_rn(__expf(a.x)); hk[1] = __float2half_rn(__expf(a.y));
        hk[2] = __float2half_rn(__expf(a.z)); hk[3] = __float2half_rn(__expf(a.w));
        hk[4] = __float2half_rn(__expf(c.x)); hk[5] = __float2half_rn(__expf(c.y));
        hk[6] = __float2half_rn(__expf(c.z)); hk[7] = __float2half_rn(__expf(c.w));
    } else {
        #pragma unroll
        for (int c = 0; c < 8; c++) {
            float v = (j + c < nc) ? __expf(mrow[j + c]) : 0.f;
            hk[c] = __float2half_rn(v);
        }
    }
    *reinterpret_cast<uint4*>(g_K + ((size_t)b << 20) + ((size_t)row << 10) + j) =
        *reinterpret_cast<const uint4*>(hk);
}

// v := 1 everywhere (initial column potential)
__global__ void init_v_kernel() {
    int idx = blockIdx.x * blockDim.x + threadIdx.x;
    if (idx < BB * MM) g_v[idx] = 1.0f;
}

// ---------------------------------------------------------------------------
// Fused pass: block = 32-row chunk of one batch. 8 warps, 4 rows each.
// Per row: warp computes rowsum(K*v) -> u_i, writes g_u, accumulates K*u into
// 32 per-lane col accumulators (lane's j set is fixed: j = p*128 + lane*4 + c).
// v is register-resident per block. Epilogue: smem stage across warps, then
// one atomicAdd per column into g_s.  grid = (32, 64), block = 256.
// ---------------------------------------------------------------------------
__global__ void __launch_bounds__(256) fused_pass_kernel(const int* __restrict__ nrows,
                                                         const int* __restrict__ ncols) {
    int b  = blockIdx.y;
    int nr = nrows[b];
    int nc = ncols[b];
    int i0 = blockIdx.x * 32;
    if (i0 >= nr || nc == 0) return;
    int npass = (nc + 127) >> 7;

    int lane = threadIdx.x & 31;
    int w    = threadIdx.x >> 5;

    // v for this lane's 32 columns, register-resident
    const float* vrow = g_v + (b << 10);
    float4 vr[8];
    #pragma unroll
    for (int p = 0; p < 8; p++)
        vr[p] = *reinterpret_cast<const float4*>(vrow + p * 128 + lane * 4);

    float acc[32];
    #pragma unroll
    for (int k = 0; k < 32; k++) acc[k] = 0.f;

    const __half* Kb = g_K + ((size_t)b << 20);

    #pragma unroll
    for (int q = 0; q < 4; q++) {
        int i = i0 + w * 4 + q;
        if (i < nr) {
            const __half* krow = Kb + ((size_t)i << 10);
            uint2 kk[8];
            float s0 = 0.f, s1 = 0.f, s2 = 0.f, s3 = 0.f;
            #pragma unroll
            for (int p = 0; p < 8; p++) {
                if (p < npass)
                    kk[p] = *reinterpret_cast<const uint2*>(krow + p * 128 + lane * 4);
                else
                    kk[p] = make_uint2(0u, 0u);
                float2 f0 = __half22float2(*reinterpret_cast<__half2*>(&kk[p].x));
                float2 f1 = __half22float2(*reinterpret_cast<__half2*>(&kk[p].y));
                s0 = fmaf(f0.x, vr[p].x, s0);
                s1 = fmaf(f0.y, vr[p].y, s1);
                s2 = fmaf(f1.x, vr[p].z, s2);
                s3 = fmaf(f1.y, vr[p].w, s3);
            }
            float sum = (s0 + s1) + (s2 + s3);
            #pragma unroll
            for (int o = 16; o; o >>= 1) sum += __shfl_xor_sync(0xffffffffu, sum, o);
            float u = (sum > 0.f) ? (1.0f / sum) : 0.f;
            if (lane == 0) g_u[(b << 10) + i] = u;
            #pragma unroll
            for (int p = 0; p < 8; p++) {
                float2 f0 = __half22float2(*reinterpret_cast<__half2*>(&kk[p].x));
                float2 f1 = __half22float2(*reinterpret_cast<__half2*>(&kk[p].y));
                acc[p * 4 + 0] = fmaf(f0.x, u, acc[p * 4 + 0]);
                acc[p * 4 + 1] = fmaf(f0.y, u, acc[p * 4 + 1]);
                acc[p * 4 + 2] = fmaf(f1.x, u, acc[p * 4 + 2]);
                acc[p * 4 + 3] = fmaf(f1.y, u, acc[p * 4 + 3]);
            }
        }
    }

    // Stage per-warp accumulators, sum across warps, one REDG per column.
    __shared__ float sm[8 * 1024];
    #pragma unroll
    for (int p = 0; p < 8; p++) {
        *reinterpret_cast<float4*>(&sm[w * 1024 + p * 128 + lane * 4]) =
            make_float4(acc[p * 4 + 0], acc[p * 4 + 1], acc[p * 4 + 2], acc[p * 4 + 3]);
    }
    __syncthreads();
    int t = threadIdx.x;
    int jmax = npass << 7;
    #pragma unroll
    for (int r = 0; r < 4; r++) {
        int j = r * 256 + t;
        if (j < jmax) {
            float s = 0.f;
            #pragma unroll
            for (int ww = 0; ww < 8; ww++) s += sm[ww * 1024 + j];
            atomicAdd(&g_s[(b << 10) + j], s);
        }
    }
}

// v_j = 1/s_j for valid cols, 0 otherwise; re-zero the accumulator.
__global__ void combine_v_kernel(const int* __restrict__ ncols) {
    int idx = blockIdx.x * blockDim.x + threadIdx.x;  // 0..65535
    int b = idx >> 10;
    int j = idx & 1023;
    float s = g_s[idx];
    g_s[idx] = 0.f;
    g_v[idx] = (j < ncols[b] && s > 0.f) ? (1.0f / s) : 0.f;
}

// ---------------------------------------------------------------------------
// Final: out = valid ? u_i * exp(m_ij) * v_j : 0 — exp recomputed in fp32.
// grid = 4096, block = 256, 16 float4/thread (full 256 MB write).
// ---------------------------------------------------------------------------
__global__ void final_kernel(const float* __restrict__ m,
                             const int* __restrict__ nrows,
                             const int* __restrict__ ncols,
                             float* __restrict__ out) {
    int b   = blockIdx.x >> 6;
    int sub = blockIdx.x & 63;
    int nr = nrows[b];
    int nc = ncols[b];
    const float* mb = m + ((size_t)b << 20);
    float*       ob = out + ((size_t)b << 20);

    #pragma unroll
    for (int k = 0; k < 16; k++) {
        int q = sub * 4096 + k * 256 + threadIdx.x;  // float4 index in batch
        int i = q >> 8;
        int j = (q & 255) << 2;
        float4 o;
        if (i >= nr || j >= nc) {
            o = make_float4(0.f, 0.f, 0.f, 0.f);
        } else {
            float4 mm = *reinterpret_cast<const float4*>(mb + ((size_t)q << 2));
            float  u  = g_u[(b << 10) + i];
            float4 vv = *reinterpret_cast<const float4*>(g_v + (b << 10) + j);
            // v_j == 0 for j >= nc, so tail elements of a boundary float4
            // are zeroed automatically (exp(m) is finite).
            o.x = __expf(mm.x) * u * vv.x;
            o.y = __expf(mm.y) * u * vv.y;
            o.z = __expf(mm.z) * u * vv.z;
            o.w = __expf(mm.w) * u * vv.w;
        }
        *reinterpret_cast<float4*>(ob + ((size_t)q << 2)) = o;
    }
}

extern "C" void kernel_launch(void* const* d_in, const int* in_sizes, int n_in,
                              void* d_out, int out_size) {
    const float* m     = (const float*)d_in[0];
    const int*   nrows = (const int*)d_in[1];
    const int*   ncols = (const int*)d_in[2];
    float* out = (float*)d_out;

    build_k_kernel<<<dim3(512, 64), 256>>>(m, nrows, ncols);
    init_v_kernel<<<256, 256>>>();

    for (int t = 0; t < 10; t++) {
        fused_pass_kernel<<<dim3(32, 64), 256>>>(nrows, ncols);
        combine_v_kernel<<<256, 256>>>(ncols);
    }

    final_kernel<<<4096, 256>>>(m, nrows, ncols, out);
}